// round 5
// baseline (speedup 1.0000x reference)
#include <cuda_runtime.h>
#include <cuda_fp16.h>

#define NROWS 32768
#define DDIM  64
#define KCB   1024
#define MT    128
#define NHT   16            // 64-code half-tiles
#define NTHREADS 256

#define O_ZQ    0
#define O_LOSS  2097152
#define O_PERP  2097153
#define O_IDX   2097154
#define O_DIST  2129922

// K layout: 192 used halves ([h1|h2|h1] vs [g1|g1|g2]), pitch 200 halves (400 B)
#define KP 200
#define HT_BYTES (64 * KP * 2)      // 25600 per 64-code half-tile

// smem byte offsets
#define S_A    0                    // 128 x KP halves = 51200
#define S_B    51200                // 2 x 25600 = 51200
#define S_E2   102400               // 1024 f32
#define S_F2   106496               // 128 f32
#define S_AV0  107008
#define S_AI0  107520
#define S_AV1  108032
#define S_AI1  108544
#define S_IDX  109056
#define S_RED  109568               // 256 f32
#define SMEM_BYTES 110592           // <= 113664 -> 2 CTAs/SM

#define ESCALE 1024.0f
#define DSCALE (-2.0f / 1024.0f)    // exact power of two

__device__ float         g_loss;
__device__ unsigned int  g_counts[KCB];
__device__ float         g_e2[KCB];
__device__ __align__(16) unsigned char g_epack[NHT * HT_BYTES];

__device__ __forceinline__ unsigned smem_u32(const void* p) {
    unsigned a;
    asm("{ .reg .u64 t; cvta.to.shared.u64 t, %1; cvt.u32.u64 %0, t; }"
        : "=r"(a) : "l"(p));
    return a;
}
__device__ __forceinline__ void cp16(unsigned dst, const void* src) {
    asm volatile("cp.async.cg.shared.global [%0], [%1], 16;" :: "r"(dst), "l"(src));
}
#define CP_COMMIT() asm volatile("cp.async.commit_group;" ::: "memory")
#define CP_WAIT0()  asm volatile("cp.async.wait_group 0;"  ::: "memory")

__device__ __forceinline__ void mma16816(float* c, const unsigned* a,
                                         unsigned b0, unsigned b1) {
    asm volatile(
        "mma.sync.aligned.m16n8k16.row.col.f32.f16.f16.f32 "
        "{%0,%1,%2,%3}, {%4,%5,%6,%7}, {%8,%9}, {%0,%1,%2,%3};"
        : "+f"(c[0]), "+f"(c[1]), "+f"(c[2]), "+f"(c[3])
        : "r"(a[0]), "r"(a[1]), "r"(a[2]), "r"(a[3]), "r"(b0), "r"(b1));
}

__device__ __forceinline__ void split2(float x, __half& a, __half& b) {
    a = __float2half_rn(x);
    b = __float2half_rn(x - __half2float(a));
}

// ---- prepack: codebook -> fp16 split [g1|g1|g2] half-tiles, e2; + zero scratch ----
__global__ void vq_prepack_kernel(const float* __restrict__ emb) {
    const int t = threadIdx.x;
    if (blockIdx.x == 32) {
        for (int i = t; i < KCB; i += NTHREADS) g_counts[i] = 0u;
        if (t == 0) g_loss = 0.0f;
        return;
    }
    const int kk = t >> 3, part = t & 7;           // 32 codes/block, 8 d-chunks
    const int k = blockIdx.x * 32 + kk;
    const float* ep = emb + (size_t)k * DDIM + part * 8;
    __half* row = (__half*)(g_epack + (size_t)(k >> 6) * HT_BYTES + (k & 63) * (KP * 2));
    float e2p = 0.0f;
    #pragma unroll
    for (int i = 0; i < 8; i += 2) {
        float x0 = ep[i], x1 = ep[i + 1];
        e2p = fmaf(x0, x0, e2p);
        e2p = fmaf(x1, x1, e2p);
        __half a0, b0, a1, b1;
        split2(x0 * ESCALE, a0, b0);
        split2(x1 * ESCALE, a1, b1);
        int d = part * 8 + i;
        *(__half2*)(row + d)       = __halves2half2(a0, a1);   // g1
        *(__half2*)(row + 64 + d)  = __halves2half2(a0, a1);   // g1 (dup)
        *(__half2*)(row + 128 + d) = __halves2half2(b0, b1);   // g2
    }
    #pragma unroll
    for (int off = 4; off > 0; off >>= 1)
        e2p += __shfl_xor_sync(0xffffffffu, e2p, off, 8);
    if (part == 0) g_e2[k] = e2p;
}

__global__ void __launch_bounds__(NTHREADS, 2)
vq_main_kernel(const float* __restrict__ z_e,
               const float* __restrict__ emb,
               float* __restrict__ zq_out,
               float* __restrict__ idx_out,
               float* __restrict__ dist_out)
{
    extern __shared__ unsigned char smem[];
    const unsigned sbase = smem_u32(smem);
    const int t = threadIdx.x, lane = t & 31, w = t >> 5;
    const int wm = w & 3, wn = w >> 2;          // warp m-quad (32 rows), n-half (32 codes)
    const int q = lane & 3, lg = lane >> 2;

    const int n0 = blockIdx.x * MT, b = n0 >> 10, hw0 = n0 & 1023;
    const float* zbase = z_e + (size_t)b * (DDIM * 1024) + hw0;

    __half* A_s  = (__half*)(smem + S_A);
    float*  e2_s = (float*)(smem + S_E2);
    float*  f2_s = (float*)(smem + S_F2);
    int*    idx_s = (int*)(smem + S_IDX);
    float*  red  = (float*)(smem + S_RED);

    // prefetch B half-tile 0
    #pragma unroll
    for (int i = 0; i < 7; ++i) {
        int c = i * NTHREADS + t;
        if (c < HT_BYTES / 16) cp16(sbase + S_B + c * 16, g_epack + c * 16);
    }
    CP_COMMIT();

    // build A = [h1|h2|h1] fp16 + f2, straight from global (2x64B sectors/warp-load)
    {
        const int m = t >> 1, hf = t & 1;
        __half* arow = A_s + m * KP;
        float f2p = 0.0f;
        #pragma unroll
        for (int i = 0; i < 32; i += 2) {
            int d = hf * 32 + i;
            float x0 = zbase[(size_t)d * 1024 + m];
            float x1 = zbase[(size_t)(d + 1) * 1024 + m];
            f2p = fmaf(x0, x0, f2p);
            f2p = fmaf(x1, x1, f2p);
            __half a0, b0, a1, b1;
            split2(x0, a0, b0);
            split2(x1, a1, b1);
            *(__half2*)(arow + d)       = __halves2half2(a0, a1);
            *(__half2*)(arow + 64 + d)  = __halves2half2(b0, b1);
            *(__half2*)(arow + 128 + d) = __halves2half2(a0, a1);
        }
        float oth = __shfl_xor_sync(0xffffffffu, f2p, 1);
        if (hf == 0) f2_s[m] = f2p + oth;
    }
    #pragma unroll
    for (int i = 0; i < 4; ++i) e2_s[i * NTHREADS + t] = g_e2[i * NTHREADS + t];
    __syncthreads();

    float bestv[4];
    int   besti[4];
    #pragma unroll
    for (int i = 0; i < 4; ++i) { bestv[i] = 3.0e38f; besti[i] = 0; }

    const float f2a0 = f2_s[wm * 32 + lg];
    const float f2b0 = f2_s[wm * 32 + lg + 8];
    const float f2a1 = f2_s[wm * 32 + 16 + lg];
    const float f2b1 = f2_s[wm * 32 + 16 + lg + 8];

    #pragma unroll 1
    for (int ht = 0; ht < NHT; ++ht) {
        const int cur = ht & 1;
        CP_WAIT0();
        __syncthreads();                 // buf[cur] visible; buf[cur^1] free
        if (ht < NHT - 1) {
            const unsigned char* src = g_epack + (size_t)(ht + 1) * HT_BYTES;
            unsigned dstb = sbase + S_B + (cur ^ 1) * HT_BYTES;
            #pragma unroll
            for (int i = 0; i < 7; ++i) {
                int c = i * NTHREADS + t;
                if (c < HT_BYTES / 16) cp16(dstb + c * 16, src + c * 16);
            }
            CP_COMMIT();
        }
        const __half* B_s = (const __half*)(smem + S_B + cur * HT_BYTES);

        float C[2][4][4];
        #pragma unroll
        for (int mt = 0; mt < 2; ++mt)
            #pragma unroll
            for (int nt = 0; nt < 4; ++nt)
                #pragma unroll
                for (int r = 0; r < 4; ++r) C[mt][nt][r] = 0.0f;

        #pragma unroll
        for (int kt = 0; kt < 12; ++kt) {
            const int k0 = kt * 16 + 2 * q;
            unsigned a[2][4];
            #pragma unroll
            for (int mt = 0; mt < 2; ++mt) {
                const int r = wm * 32 + mt * 16 + lg;
                a[mt][0] = *(const unsigned*)(A_s + r * KP + k0);
                a[mt][1] = *(const unsigned*)(A_s + (r + 8) * KP + k0);
                a[mt][2] = *(const unsigned*)(A_s + r * KP + k0 + 8);
                a[mt][3] = *(const unsigned*)(A_s + (r + 8) * KP + k0 + 8);
            }
            #pragma unroll
            for (int nt = 0; nt < 4; ++nt) {
                const int n = wn * 32 + nt * 8 + lg;
                unsigned b0 = *(const unsigned*)(B_s + n * KP + k0);
                unsigned b1 = *(const unsigned*)(B_s + n * KP + k0 + 8);
                mma16816(C[0][nt], a[0], b0, b1);
                mma16816(C[1][nt], a[1], b0, b1);
            }
        }

        // epilogue: distances, argmin, direct float2 stores
        #pragma unroll
        for (int mt = 0; mt < 2; ++mt) {
            const int r = wm * 32 + mt * 16 + lg;
            const float f2a = mt ? f2a1 : f2a0;
            const float f2b = mt ? f2b1 : f2b0;
            float* dra = dist_out + (size_t)(n0 + r) * KCB;
            float* drb = dist_out + (size_t)(n0 + r + 8) * KCB;
            #pragma unroll
            for (int nt = 0; nt < 4; ++nt) {
                const int col = ht * 64 + wn * 32 + nt * 8 + 2 * q;
                const float e2x = e2_s[col], e2y = e2_s[col + 1];
                float d0 = fmaf(DSCALE, C[mt][nt][0], f2a + e2x);
                float d1 = fmaf(DSCALE, C[mt][nt][1], f2a + e2y);
                float d2 = fmaf(DSCALE, C[mt][nt][2], f2b + e2x);
                float d3 = fmaf(DSCALE, C[mt][nt][3], f2b + e2y);
                if (d0 < bestv[mt * 2])     { bestv[mt * 2] = d0;     besti[mt * 2] = col; }
                if (d1 < bestv[mt * 2])     { bestv[mt * 2] = d1;     besti[mt * 2] = col + 1; }
                if (d2 < bestv[mt * 2 + 1]) { bestv[mt * 2 + 1] = d2; besti[mt * 2 + 1] = col; }
                if (d3 < bestv[mt * 2 + 1]) { bestv[mt * 2 + 1] = d3; besti[mt * 2 + 1] = col + 1; }
                *(float2*)(dra + col) = make_float2(d0, d1);
                *(float2*)(drb + col) = make_float2(d2, d3);
            }
        }
    }
    __syncthreads();

    // quad argmin reduction (tie -> lowest index), then cross-half combine
    #pragma unroll
    for (int i = 0; i < 4; ++i) {
        float v = bestv[i];
        int  bi = besti[i];
        #pragma unroll
        for (int off = 2; off > 0; off >>= 1) {
            float ov = __shfl_down_sync(0xffffffffu, v, off, 4);
            int   oi = __shfl_down_sync(0xffffffffu, bi, off, 4);
            if (ov < v || (ov == v && oi < bi)) { v = ov; bi = oi; }
        }
        if (q == 0) {
            const int r = wm * 32 + (i >> 1) * 16 + (i & 1) * 8 + lg;
            ((float*)(smem + (wn ? S_AV1 : S_AV0)))[r] = v;
            ((int*)  (smem + (wn ? S_AI1 : S_AI0)))[r] = bi;
        }
    }
    __syncthreads();

    if (t < 128) {
        float v0 = ((float*)(smem + S_AV0))[t], v1 = ((float*)(smem + S_AV1))[t];
        int   i0 = ((int*)(smem + S_AI0))[t],   i1 = ((int*)(smem + S_AI1))[t];
        int bi = (v1 < v0 || (v1 == v0 && i1 < i0)) ? i1 : i0;
        idx_s[t] = bi;
        idx_out[n0 + t] = (float)bi;
        atomicAdd(&g_counts[bi], 1u);
    }
    __syncthreads();

    // z_q gather/scatter + loss partial (re-read z_e from L2/DRAM)
    float lsum = 0.0f;
    {
        const int m = t >> 1, hf = t & 1;
        const int bi = idx_s[m];
        const float* erow = emb + (size_t)bi * DDIM;
        float* zq_base = zq_out + (size_t)b * (DDIM * 1024) + hw0;
        #pragma unroll
        for (int i = 0; i < 32; ++i) {
            int d = hf * 32 + i;
            float v  = erow[d];
            float fv = zbase[(size_t)d * 1024 + m];
            float df = v - fv;
            lsum = fmaf(df, df, lsum);
            zq_base[(size_t)d * 1024 + m] = v;
        }
    }
    red[t] = lsum;
    __syncthreads();
    #pragma unroll
    for (int s = 128; s > 0; s >>= 1) {
        if (t < s) red[t] += red[t + s];
        __syncthreads();
    }
    if (t == 0) atomicAdd(&g_loss, red[0]);
}

__global__ void vq_finalize_kernel(float* __restrict__ loss_out,
                                   float* __restrict__ perp_out)
{
    __shared__ float red[KCB];
    int t = threadIdx.x;
    float c = (float)g_counts[t];
    float p = c * (1.0f / (float)NROWS);
    red[t] = p * logf(p + 1e-10f);
    __syncthreads();
    #pragma unroll
    for (int s = KCB / 2; s > 0; s >>= 1) {
        if (t < s) red[t] += red[t + s];
        __syncthreads();
    }
    if (t == 0) {
        *perp_out = expf(-red[0]);
        *loss_out = g_loss * (1.25f / (float)(NROWS * DDIM));
    }
}

extern "C" void kernel_launch(void* const* d_in, const int* in_sizes, int n_in,
                              void* d_out, int out_size)
{
    const float* z_e = (const float*)d_in[0];
    const float* emb = (const float*)d_in[1];
    float* out = (float*)d_out;

    cudaFuncSetAttribute(vq_main_kernel,
                         cudaFuncAttributeMaxDynamicSharedMemorySize, SMEM_BYTES);

    vq_prepack_kernel<<<33, NTHREADS>>>(emb);
    vq_main_kernel<<<NROWS / MT, NTHREADS, SMEM_BYTES>>>(
        z_e, emb, out + O_ZQ, out + O_IDX, out + O_DIST);
    vq_finalize_kernel<<<1, KCB>>>(out + O_LOSS, out + O_PERP);
}